// round 7
// baseline (speedup 1.0000x reference)
#include <cuda_runtime.h>
#include <cstdint>
#include <cstddef>

constexpr int B = 32, S = 1024, D = 256, F = 256, T = 8192;
constexpr int NCHUNK = 12;       // 3 k-shifts * 4 d-chunks of 64 (int8 bytes)
constexpr int TT = 32;

// dynamic smem: two 40KB buffers | params 8KB | masters 64KB
// buf: aH 4K | aL 4K | bH 16K | bL 16K
constexpr int BUF_SZ     = 40960;
constexpr int PARAM_OFF  = 81920;
constexpr int MASTER_OFF = 90112;
constexpr int SMEM_TOTAL = 155648;

// ---------------- device scratch ----------------
__device__ __align__(16) signed char g_xq1[(size_t)B*S*256];
__device__ __align__(16) signed char g_xq2[(size_t)B*S*256];
__device__ float g_xs[B*S];
__device__ __align__(16) signed char g_h1q1[(size_t)B*S*256];
__device__ __align__(16) signed char g_h1q2[(size_t)B*S*256];
__device__ float g_h1s[B*S];
__device__ __align__(16) signed char g_wq1[2*12*16384];   // pre-swizzled B tiles (SW64)
__device__ __align__(16) signed char g_wq2[2*12*16384];
__device__ float g_ws[2*256];
__device__ int g_cum[B*S];

// ---------------- helpers ----------------
__device__ __forceinline__ uint32_t swz64(uint32_t off){ return off ^ ((off>>3)&0x30); }
__device__ __forceinline__ uint32_t s2u(const void* p){
    uint32_t a; asm("{ .reg .u64 t; cvta.to.shared.u64 t, %1; cvt.u32.u64 %0, t; }" : "=r"(a) : "l"(p)); return a;
}
__device__ __forceinline__ void cpa16(uint32_t dst, const void* src){
    asm volatile("cp.async.cg.shared.global [%0], [%1], 16;" :: "r"(dst), "l"(src) : "memory");
}
__device__ __forceinline__ void cpa16z(uint32_t dst, const void* src, int valid){
    int sz = valid ? 16 : 0;
    asm volatile("cp.async.cg.shared.global [%0], [%1], 16, %2;" :: "r"(dst), "l"(src), "r"(sz) : "memory");
}
__device__ __forceinline__ void cpa_commit(){ asm volatile("cp.async.commit_group;" ::: "memory"); }
template<int N> __device__ __forceinline__ void cpa_wait(){ asm volatile("cp.async.wait_group %0;" :: "n"(N) : "memory"); }

__device__ __forceinline__ void ldm_x4(uint32_t* r, uint32_t addr){
    asm volatile("ldmatrix.sync.aligned.m8n8.x4.shared.b16 {%0,%1,%2,%3}, [%4];"
        : "=r"(r[0]),"=r"(r[1]),"=r"(r[2]),"=r"(r[3]) : "r"(addr));
}
__device__ __forceinline__ void mma_s8(int* c, const uint32_t* a, const uint32_t* b){
    asm volatile("mma.sync.aligned.m16n8k32.row.col.s32.s8.s8.s32 "
        "{%0,%1,%2,%3}, {%4,%5,%6,%7}, {%8,%9}, {%0,%1,%2,%3};"
        : "+r"(c[0]),"+r"(c[1]),"+r"(c[2]),"+r"(c[3])
        : "r"(a[0]),"r"(a[1]),"r"(a[2]),"r"(a[3]), "r"(b[0]),"r"(b[1]));
}
// A frag (m16k32 s8) from [row][64B] SW64 region; byte offsets identical to bf16 m16k16 path
__device__ __forceinline__ void ld_afrag(uint32_t* r, uint32_t region, int mbase, int ks, int lane){
    int i = lane>>3, lm = lane&7;
    int row = mbase + lm + (i&1)*8;
    int kb  = ks*32 + (i>>1)*16;
    ldm_x4(r, region + swz64((uint32_t)(row*64 + kb)));
}
// B frags: two n8 x k32 frags; r0,r1 = n0 (k0-15,k16-31), r2,r3 = n8
__device__ __forceinline__ void ld_bfrag(uint32_t* r, uint32_t region, int nbase, int ks, int lane){
    int i = lane>>3, lm = lane&7;
    int row = nbase + lm + (i>>1)*8;
    int kb  = ks*32 + (i&1)*16;
    ldm_x4(r, region + swz64((uint32_t)(row*64 + kb)));
}
__device__ __forceinline__ int q_rn(float v){ return __float2int_rn(v); }

// ---------------- prep: x fp32 -> two-level s8 (per-row scale) ----------------
__global__ void prep_x(const float* __restrict__ x){
    int row  = blockIdx.x*8 + (threadIdx.x>>5);    // 0..32767
    int lane = threadIdx.x & 31;
    const float4* xp = (const float4*)(x + (size_t)row*256 + lane*8);
    float4 v0 = xp[0], v1 = xp[1];
    float vv[8] = {v0.x,v0.y,v0.z,v0.w,v1.x,v1.y,v1.z,v1.w};
    float m = 0.f;
#pragma unroll
    for (int j = 0; j < 8; j++) m = fmaxf(m, fabsf(vv[j]));
#pragma unroll
    for (int o = 16; o; o >>= 1) m = fmaxf(m, __shfl_xor_sync(0xffffffffu, m, o));
    float s1 = fmaxf(m, 1e-20f) * (1.f/127.f);
    float inv1 = 1.f/s1, inv2 = 254.f*inv1;
    uint32_t p1[2] = {0,0}, p2[2] = {0,0};
#pragma unroll
    for (int j = 0; j < 8; j++){
        int q1 = q_rn(vv[j]*inv1);
        float r = vv[j] - (float)q1*s1;
        int q2 = q_rn(r*inv2);
        p1[j>>2] |= ((uint32_t)(q1 & 0xff)) << ((j&3)*8);
        p2[j>>2] |= ((uint32_t)(q2 & 0xff)) << ((j&3)*8);
    }
    *(uint2*)(g_xq1 + (size_t)row*256 + lane*8) = make_uint2(p1[0], p1[1]);
    *(uint2*)(g_xq2 + (size_t)row*256 + lane*8) = make_uint2(p2[0], p2[1]);
    if (lane == 0) g_xs[row] = s1;
}

// ---------------- prep: weights -> two-level s8, pre-swizzled SW64 tiles ----------------
// tile = cv*12 + kk*4 + dchunk : 256 rows(f) x 64B(d), 16KB each
__global__ void prep_w(const float* __restrict__ w1, const float* __restrict__ w2){
    int f    = blockIdx.x*8 + (threadIdx.x>>5);    // 0..511
    int lane = threadIdx.x & 31;
    int cv = f >> 8, fl = f & 255;
    const float* w = (cv ? w2 : w1) + (size_t)fl*768;
    float vals[24]; float m = 0.f;
#pragma unroll
    for (int j = 0; j < 24; j++){ vals[j] = w[lane + 32*j]; m = fmaxf(m, fabsf(vals[j])); }
#pragma unroll
    for (int o = 16; o; o >>= 1) m = fmaxf(m, __shfl_xor_sync(0xffffffffu, m, o));
    float s1 = fmaxf(m, 1e-20f) * (1.f/127.f);
    float inv1 = 1.f/s1, inv2 = 254.f*inv1;
#pragma unroll
    for (int j = 0; j < 24; j++){
        int e = lane + 32*j;         // e = d*3 + kk
        int d = e/3, kk = e - d*3;
        int q1 = q_rn(vals[j]*inv1);
        float r = vals[j] - (float)q1*s1;
        int q2 = q_rn(r*inv2);
        int tile = cv*12 + kk*4 + (d>>6);
        uint32_t off = swz64((uint32_t)(fl*64 + (d & 63)));
        g_wq1[(size_t)tile*16384 + off] = (signed char)q1;
        g_wq2[(size_t)tile*16384 + off] = (signed char)q2;
    }
    if (lane == 0) g_ws[f] = s1;
}

// ---------------- fused conv+bias+relu+LN (+linear / +requant) on s8 IMMA ----------------
// Tile M=64 x N=256, 256 threads, warp grid 2(M) x 4(N), warp tile 32x64.
template<int MODE>
__global__ void __launch_bounds__(256)
conv_mma_kernel(const float* __restrict__ cb, const float* __restrict__ lg,
                const float* __restrict__ lb, const float* __restrict__ lw,
                const float* __restrict__ lbb,
                float* __restrict__ out_logdur)
{
    extern __shared__ __align__(1024) unsigned char dyn[];
    const int tid  = threadIdx.x;
    const int wid  = tid >> 5;
    const int lane = tid & 31;
    const int b    = blockIdx.x >> 4;
    const int s0   = (blockIdx.x & 15) * 64;
    const uint32_t sb = s2u(dyn);
    const int wm = wid >> 2, wn = wid & 3;
    const int l4 = lane & 3, lq = lane >> 2;

    float* p_bias = (float*)(dyn + PARAM_OFF);
    float* p_g    = p_bias + 256;
    float* p_b2   = p_g + 256;
    float* p_lw   = p_b2 + 256;
    float* p_ws   = p_lw + 256;
    float* s_as   = p_ws + 256;      // 66 halo scales
    float* s_s1   = s_as + 80;       // 64 (MODE 0 requant scales)
    float* m_acc  = (float*)(dyn + MASTER_OFF);   // [64][256]

    const signed char* g_aq1 = MODE ? g_h1q1 : g_xq1;
    const signed char* g_aq2 = MODE ? g_h1q2 : g_xq2;
    const float*       g_asx = MODE ? g_h1s  : g_xs;

    p_bias[tid] = cb[tid]; p_g[tid] = lg[tid]; p_b2[tid] = lb[tid];
    p_ws[tid] = g_ws[MODE*256 + tid];
    if (MODE == 1) p_lw[tid] = lw[tid];
    if (tid < 66){
        int s = s0 - 1 + tid;
        s_as[tid] = (s >= 0 && s < S) ? g_asx[b*S + s] : 0.f;
    }

    auto stage = [&](int c){
        const int buf = c & 1, kk = c >> 2, dc = c & 3, d0 = dc * 64;
        const uint32_t bufb = sb + buf*BUF_SZ;
        const int tile = MODE*12 + kk*4 + dc;
        const signed char* s1p = g_wq1 + (size_t)tile*16384;
        const signed char* s2p = g_wq2 + (size_t)tile*16384;
#pragma unroll
        for (int i = 0; i < 4; i++){
            uint32_t o = (uint32_t)(tid + i*256) << 4;
            cpa16(bufb + 8192  + o, s1p + o);
            cpa16(bufb + 24576 + o, s2p + o);
        }
        {
            int r = tid >> 2, q = tid & 3;
            int s = s0 + r + kk - 1;
            int valid = ((unsigned)s < (unsigned)S);
            size_t eoff = (size_t)(b*S + (valid ? s : 0))*256 + d0 + q*16;
            uint32_t doff = swz64((uint32_t)(r*64 + q*16));
            cpa16z(bufb + doff,        g_aq1 + eoff, valid);
            cpa16z(bufb + 4096 + doff, g_aq2 + eoff, valid);
        }
    };

    int accH[2][4][2][4], accM[2][4][2][4];
#pragma unroll
    for (int mt=0;mt<2;mt++)
#pragma unroll
        for (int np=0;np<4;np++)
#pragma unroll
            for (int h=0;h<2;h++)
#pragma unroll
                for (int e=0;e<4;e++){ accH[mt][np][h][e]=0; accM[mt][np][h][e]=0; }

    stage(0); cpa_commit();

    for (int c = 0; c < NCHUNK; c++){
        if (c + 1 < NCHUNK){ stage(c+1); cpa_commit(); cpa_wait<1>(); }
        else cpa_wait<0>();
        __syncthreads();

        const uint32_t rAh = sb + (c&1)*BUF_SZ;
        const uint32_t rAl = rAh + 4096;
        const uint32_t rBh = rAh + 8192;
        const uint32_t rBl = rAh + 24576;

#pragma unroll
        for (int ks = 0; ks < 2; ks++){
            uint32_t aH[2][4], aL[2][4], bH[4][4];
#pragma unroll
            for (int mt=0;mt<2;mt++) ld_afrag(aH[mt], rAh, wm*32+mt*16, ks, lane);
#pragma unroll
            for (int mt=0;mt<2;mt++) ld_afrag(aL[mt], rAl, wm*32+mt*16, ks, lane);
#pragma unroll
            for (int np=0;np<4;np++) ld_bfrag(bH[np], rBh, wn*64+np*16, ks, lane);
            // hi*hi
#pragma unroll
            for (int mt=0;mt<2;mt++)
#pragma unroll
                for (int np=0;np<4;np++){
                    mma_s8(accH[mt][np][0], aH[mt], &bH[np][0]);
                    mma_s8(accH[mt][np][1], aH[mt], &bH[np][2]);
                }
            // mid terms: hi*lo + lo*hi (shared scale -> shared accumulator)
#pragma unroll
            for (int np=0;np<4;np++){
                uint32_t bl[4];
                ld_bfrag(bl, rBl, wn*64+np*16, ks, lane);
#pragma unroll
                for (int mt=0;mt<2;mt++){
                    mma_s8(accM[mt][np][0], aH[mt], &bl[0]);
                    mma_s8(accM[mt][np][1], aH[mt], &bl[2]);
                    mma_s8(accM[mt][np][0], aL[mt], &bH[np][0]);
                    mma_s8(accM[mt][np][1], aL[mt], &bH[np][2]);
                }
            }
        }

        // merge into fp32 masters at end of each k-shift (A-row scale constant per shift)
        if ((c & 3) == 3){
            const int kk2 = c >> 2;
#pragma unroll
            for (int mt=0;mt<2;mt++)
#pragma unroll
                for (int np=0;np<4;np++)
#pragma unroll
                    for (int h=0;h<2;h++){
                        int cb0 = wn*64 + np*16 + h*8 + l4*2;
                        float sbv[2] = { p_ws[cb0], p_ws[cb0+1] };
#pragma unroll
                        for (int rh=0;rh<2;rh++){
                            int row = wm*32 + mt*16 + lq + rh*8;
                            float sa = s_as[row + kk2];
#pragma unroll
                            for (int e=0;e<2;e++){
                                float sH = sa * sbv[e];
                                float v = (float)accH[mt][np][h][rh*2+e]*sH
                                        + (float)accM[mt][np][h][rh*2+e]*(sH*(1.f/254.f));
                                int id = (((mt*4+np)*2+h)*2+rh)*2+e;
                                float* mp = m_acc + id*256 + tid;
                                if (kk2 == 0) *mp = v; else *mp += v;
                                accH[mt][np][h][rh*2+e] = 0;
                                accM[mt][np][h][rh*2+e] = 0;
                            }
                        }
                    }
        }
        __syncthreads();
    }

    // ---------------- epilogue ----------------
    float vv[64];
#pragma unroll
    for (int id=0; id<64; id++) vv[id] = m_acc[id*256 + tid];

    float* redS = (float*)dyn;           // [64][4]
    float* redQ = redS + 256;            // [64][4]
    float* s_mu = redQ + 256;            // [64]
    float* s_rs = s_mu + 64;             // [64]

#pragma unroll
    for (int mt=0;mt<2;mt++)
#pragma unroll
        for (int rh=0;rh<2;rh++){
            float sm_=0.f, sq_=0.f;
#pragma unroll
            for (int np=0;np<4;np++)
#pragma unroll
                for (int h=0;h<2;h++){
                    int cb_ = wn*64 + np*16 + h*8 + l4*2;
#pragma unroll
                    for (int e=0;e<2;e++){
                        int id = (((mt*4+np)*2+h)*2+rh)*2+e;
                        float v = fmaxf(vv[id] + p_bias[cb_+e], 0.f);
                        sm_ += v; sq_ += v*v;
                    }
                }
            sm_ += __shfl_xor_sync(0xffffffffu, sm_, 1);
            sm_ += __shfl_xor_sync(0xffffffffu, sm_, 2);
            sq_ += __shfl_xor_sync(0xffffffffu, sq_, 1);
            sq_ += __shfl_xor_sync(0xffffffffu, sq_, 2);
            if (l4 == 0){
                int row = wm*32 + mt*16 + lq + rh*8;
                redS[row*4 + wn] = sm_;
                redQ[row*4 + wn] = sq_;
            }
        }
    __syncthreads();
    if (tid < 64){
        float sm_ = redS[tid*4]+redS[tid*4+1]+redS[tid*4+2]+redS[tid*4+3];
        float sq_ = redQ[tid*4]+redQ[tid*4+1]+redQ[tid*4+2]+redQ[tid*4+3];
        float mu  = sm_ * (1.f/256.f);
        s_mu[tid] = mu;
        s_rs[tid] = rsqrtf(sq_ * (1.f/256.f) - mu*mu + 1e-5f);
    }
    __syncthreads();

    if (MODE == 0){
        // rowmax of LN output for requantization
#pragma unroll
        for (int mt=0;mt<2;mt++)
#pragma unroll
            for (int rh=0;rh<2;rh++){
                int row = wm*32 + mt*16 + lq + rh*8;
                float mu = s_mu[row], rs = s_rs[row];
                float mx = 0.f;
#pragma unroll
                for (int np=0;np<4;np++)
#pragma unroll
                    for (int h=0;h<2;h++){
                        int cb_ = wn*64 + np*16 + h*8 + l4*2;
#pragma unroll
                        for (int e=0;e<2;e++){
                            int id = (((mt*4+np)*2+h)*2+rh)*2+e;
                            float y = (fmaxf(vv[id]+p_bias[cb_+e],0.f)-mu)*rs*p_g[cb_+e] + p_b2[cb_+e];
                            mx = fmaxf(mx, fabsf(y));
                        }
                    }
                mx = fmaxf(mx, __shfl_xor_sync(0xffffffffu, mx, 1));
                mx = fmaxf(mx, __shfl_xor_sync(0xffffffffu, mx, 2));
                if (l4 == 0) redS[row*4 + wn] = mx;
            }
        __syncthreads();
        if (tid < 64){
            float rmax = fmaxf(fmaxf(redS[tid*4],redS[tid*4+1]),fmaxf(redS[tid*4+2],redS[tid*4+3]));
            float s1 = fmaxf(rmax, 1e-20f) * (1.f/127.f);
            s_s1[tid] = s1;
            g_h1s[b*S + s0 + tid] = s1;
        }
        __syncthreads();
        // quantize + store
#pragma unroll
        for (int mt=0;mt<2;mt++)
#pragma unroll
            for (int np=0;np<4;np++)
#pragma unroll
                for (int h=0;h<2;h++){
                    int cb_ = wn*64 + np*16 + h*8 + l4*2;
                    float g0 = p_g[cb_], g1 = p_g[cb_+1];
                    float o0 = p_b2[cb_], o1 = p_b2[cb_+1];
                    float bb0 = p_bias[cb_], bb1 = p_bias[cb_+1];
#pragma unroll
                    for (int rh=0;rh<2;rh++){
                        int row = wm*32 + mt*16 + lq + rh*8;
                        float mu = s_mu[row], rs = s_rs[row];
                        float s1 = s_s1[row];
                        float inv1 = 1.f/s1, inv2 = 254.f*inv1;
                        int id0 = (((mt*4+np)*2+h)*2+rh)*2;
                        float y0 = (fmaxf(vv[id0]+bb0,0.f)-mu)*rs*g0 + o0;
                        float y1 = (fmaxf(vv[id0+1]+bb1,0.f)-mu)*rs*g1 + o1;
                        int q10 = q_rn(y0*inv1); float r0 = y0 - (float)q10*s1; int q20 = q_rn(r0*inv2);
                        int q11 = q_rn(y1*inv1); float r1 = y1 - (float)q11*s1; int q21 = q_rn(r1*inv2);
                        size_t byo = (size_t)(b*S + s0 + row)*256 + cb_;
                        *(unsigned short*)(g_h1q1 + byo) =
                            (unsigned short)((q10 & 0xff) | ((q11 & 0xff) << 8));
                        *(unsigned short*)(g_h1q2 + byo) =
                            (unsigned short)((q20 & 0xff) | ((q21 & 0xff) << 8));
                    }
                }
    } else {
#pragma unroll
        for (int mt=0;mt<2;mt++)
#pragma unroll
            for (int rh=0;rh<2;rh++){
                int row = wm*32 + mt*16 + lq + rh*8;
                float mu = s_mu[row], rs = s_rs[row];
                float dt = 0.f;
#pragma unroll
                for (int np=0;np<4;np++)
#pragma unroll
                    for (int h=0;h<2;h++){
                        int cb_ = wn*64 + np*16 + h*8 + l4*2;
#pragma unroll
                        for (int e=0;e<2;e++){
                            int id = (((mt*4+np)*2+h)*2+rh)*2+e;
                            float y = (fmaxf(vv[id]+p_bias[cb_+e],0.f)-mu)*rs*p_g[cb_+e] + p_b2[cb_+e];
                            dt += y * p_lw[cb_+e];
                        }
                    }
                dt += __shfl_xor_sync(0xffffffffu, dt, 1);
                dt += __shfl_xor_sync(0xffffffffu, dt, 2);
                if (l4 == 0) redS[row*4 + wn] = dt;
            }
        __syncthreads();
        if (tid < 64){
            float d = redS[tid*4]+redS[tid*4+1]+redS[tid*4+2]+redS[tid*4+3];
            out_logdur[(size_t)b*S + s0 + tid] = d + lbb[0];
        }
    }
}

// ---------------- scan ----------------
__global__ void scan_kernel(const int* __restrict__ dur,
                            const int* __restrict__ maxlen_p,
                            float* __restrict__ out_dur,
                            float* __restrict__ out_mel)
{
    __shared__ int sa[S];
    const int b = blockIdx.x, tid = threadIdx.x;
    int v = dur[b*S + tid];
    out_dur[b*S + tid] = (float)v;
    sa[tid] = v;
    __syncthreads();
    for (int off = 1; off < S; off <<= 1) {
        int t = sa[tid];
        int u = (tid >= off) ? sa[tid - off] : 0;
        __syncthreads();
        sa[tid] = t + u;
        __syncthreads();
    }
    g_cum[b*S + tid] = sa[tid];
    if (tid == S - 1) out_mel[b] = (float)min(sa[tid], maxlen_p[0]);
}

// ---------------- gather ----------------
__global__ void __launch_bounds__(256)
gather_kernel(const float* __restrict__ x,
              const int* __restrict__ maxlen_p,
              float* __restrict__ out)
{
    __shared__ int cum[S];
    __shared__ int srcs[TT];
    const int b  = blockIdx.x / (T / TT);
    const int t0 = (blockIdx.x % (T / TT)) * TT;
    const int tid = threadIdx.x;
    for (int i = tid; i < S; i += 256) cum[i] = g_cum[b*S + i];
    __syncthreads();
    const int mel = min(cum[S-1], maxlen_p[0]);
    if (tid < TT) {
        int t = t0 + tid;
        int lo = 0, hi = S;
        while (lo < hi) {
            int mid = (lo + hi) >> 1;
            if (cum[mid] <= t) lo = mid + 1; else hi = mid;
        }
        srcs[tid] = min(lo, S - 1);
    }
    __syncthreads();
    const int wi = tid >> 5, lane = tid & 31;
    const float4* __restrict__ x4 = (const float4*)x;
    float4* __restrict__ o4 = (float4*)out;
    for (int r = wi; r < TT; r += 8) {
        int t = t0 + r;
        float4* dst = o4 + ((size_t)b*T + t) * (D/4);
        if (t < mel) {
            const float4* src = x4 + ((size_t)b*S + srcs[r]) * (D/4);
            dst[lane]      = src[lane];
            dst[lane + 32] = src[lane + 32];
        } else {
            float4 z = make_float4(0.f,0.f,0.f,0.f);
            dst[lane]      = z;
            dst[lane + 32] = z;
        }
    }
}

extern "C" void kernel_launch(void* const* d_in, const int* in_sizes, int n_in,
                              void* d_out, int out_size)
{
    const float* x        = (const float*)d_in[0];
    const int*   duration = (const int*)d_in[2];
    const int*   maxlen   = (const int*)d_in[3];
    const float* w1  = (const float*)d_in[4];
    const float* b1  = (const float*)d_in[5];
    const float* g1  = (const float*)d_in[6];
    const float* be1 = (const float*)d_in[7];
    const float* w2  = (const float*)d_in[8];
    const float* b2  = (const float*)d_in[9];
    const float* g2  = (const float*)d_in[10];
    const float* be2 = (const float*)d_in[11];
    const float* lw  = (const float*)d_in[12];
    const float* lbb = (const float*)d_in[13];

    float* out        = (float*)d_out;
    float* out_logdur = out + (size_t)B*T*D;
    float* out_dur    = out_logdur + (size_t)B*S;
    float* out_mel    = out_dur + (size_t)B*S;

    static int s_init = 0;
    static cudaStream_t s_main = nullptr, s_side = nullptr;
    static cudaEvent_t evF = nullptr, evM = nullptr, evS = nullptr, evW = nullptr;
    if (!s_init) {
        cudaFuncSetAttribute(conv_mma_kernel<0>, cudaFuncAttributeMaxDynamicSharedMemorySize, SMEM_TOTAL);
        cudaFuncSetAttribute(conv_mma_kernel<1>, cudaFuncAttributeMaxDynamicSharedMemorySize, SMEM_TOTAL);
        bool ok = cudaStreamCreateWithFlags(&s_main, cudaStreamNonBlocking) == cudaSuccess &&
                  cudaStreamCreateWithFlags(&s_side, cudaStreamNonBlocking) == cudaSuccess &&
                  cudaEventCreateWithFlags(&evF, cudaEventDisableTiming) == cudaSuccess &&
                  cudaEventCreateWithFlags(&evM, cudaEventDisableTiming) == cudaSuccess &&
                  cudaEventCreateWithFlags(&evS, cudaEventDisableTiming) == cudaSuccess &&
                  cudaEventCreateWithFlags(&evW, cudaEventDisableTiming) == cudaSuccess;
        if (!ok) { s_main = nullptr; s_side = nullptr; }
        s_init = 1;
    }

    if (s_main) {
        cudaEventRecord(evF, 0);
        cudaStreamWaitEvent(s_main, evF, 0);
        cudaStreamWaitEvent(s_side, evF, 0);

        // Side: prep_w, then scan + gather (hide under convs)
        prep_w<<<64, 256, 0, s_side>>>(w1, w2);
        cudaEventRecord(evW, s_side);
        scan_kernel<<<B, 1024, 0, s_side>>>(duration, maxlen, out_dur, out_mel);
        gather_kernel<<<B*(T/TT), 256, 0, s_side>>>(x, maxlen, out);
        cudaEventRecord(evS, s_side);

        // Main: prep_x, then conv chain
        prep_x<<<4096, 256, 0, s_main>>>(x);
        cudaStreamWaitEvent(s_main, evW, 0);
        conv_mma_kernel<0><<<512, 256, SMEM_TOTAL, s_main>>>(b1, g1, be1, nullptr, nullptr, nullptr);
        conv_mma_kernel<1><<<512, 256, SMEM_TOTAL, s_main>>>(b2, g2, be2, lw, lbb, out_logdur);
        cudaEventRecord(evM, s_main);

        cudaStreamWaitEvent(0, evS, 0);
        cudaStreamWaitEvent(0, evM, 0);
    } else {
        prep_x<<<4096, 256>>>(x);
        prep_w<<<64, 256>>>(w1, w2);
        conv_mma_kernel<0><<<512, 256, SMEM_TOTAL>>>(b1, g1, be1, nullptr, nullptr, nullptr);
        conv_mma_kernel<1><<<512, 256, SMEM_TOTAL>>>(b2, g2, be2, lw, lbb, out_logdur);
        scan_kernel<<<B, 1024>>>(duration, maxlen, out_dur, out_mel);
        gather_kernel<<<B*(T/TT), 256>>>(x, maxlen, out);
    }
}

// round 8
// speedup vs baseline: 3.5782x; 3.5782x over previous
#include <cuda_runtime.h>
#include <cuda_fp16.h>
#include <cstdint>
#include <cstddef>
#include <cstring>

constexpr int B = 32, S = 1024, D = 256, F = 256, T = 8192;
constexpr int NCHUNK = 24;       // 3 k-shifts * 8 d-chunks of 32
constexpr int TT = 32;           // gather rows per block

// dynamic smem (bytes): two 24KB chunk buffers + 4KB params
// buf: aHi 4K | aLo 4K | bHi 16K
constexpr int BUF_SZ    = 24576;
constexpr int PARAM_OFF = 49152;
constexpr int SMEM_TOTAL = 53248;

// ---------------- device scratch (no allocation allowed) ----------------
__device__ __align__(16) uint32_t g_h1_hi[(size_t)B*S*128];   // fp16 pairs
__device__ __align__(16) uint32_t g_h1_lo[(size_t)B*S*128];
__device__ __align__(16) uint32_t g_x_hi[(size_t)B*S*128];
__device__ __align__(16) uint32_t g_x_lo[(size_t)B*S*128];
__device__ __align__(16) unsigned char g_wB_hi[2*24*16384];   // pre-swizzled fp16 B tiles (SW64)
__device__ int g_cum[B*S];

// ---------------- helpers ----------------
__device__ __forceinline__ uint32_t swz64(uint32_t off){ return off ^ ((off>>3)&0x30); }
__device__ __forceinline__ uint32_t s2u(const void* p){
    uint32_t a; asm("{ .reg .u64 t; cvta.to.shared.u64 t, %1; cvt.u32.u64 %0, t; }" : "=r"(a) : "l"(p)); return a;
}
__device__ __forceinline__ unsigned short h_bits(__half h){ unsigned short u; memcpy(&u,&h,2); return u; }
__device__ __forceinline__ void h16split(float v, unsigned short& h, unsigned short& l){
    __half hb = __float2half_rn(v);
    float r = v - __half2float(hb);
    __half lb = __float2half_rn(r);
    h = h_bits(hb); l = h_bits(lb);
}

__device__ __forceinline__ void cpa16(uint32_t dst, const void* src){
    asm volatile("cp.async.cg.shared.global [%0], [%1], 16;" :: "r"(dst), "l"(src) : "memory");
}
__device__ __forceinline__ void cpa16z(uint32_t dst, const void* src, int valid){
    int sz = valid ? 16 : 0;
    asm volatile("cp.async.cg.shared.global [%0], [%1], 16, %2;" :: "r"(dst), "l"(src), "r"(sz) : "memory");
}
__device__ __forceinline__ void cpa_commit(){ asm volatile("cp.async.commit_group;" ::: "memory"); }
template<int N> __device__ __forceinline__ void cpa_wait(){ asm volatile("cp.async.wait_group %0;" :: "n"(N) : "memory"); }

__device__ __forceinline__ void ldm_x4(uint32_t* r, uint32_t addr){
    asm volatile("ldmatrix.sync.aligned.m8n8.x4.shared.b16 {%0,%1,%2,%3}, [%4];"
        : "=r"(r[0]),"=r"(r[1]),"=r"(r[2]),"=r"(r[3]) : "r"(addr));
}
__device__ __forceinline__ void mma_f16(float* c, const uint32_t* a, const uint32_t* b){
    asm volatile("mma.sync.aligned.m16n8k16.row.col.f32.f16.f16.f32 "
        "{%0,%1,%2,%3}, {%4,%5,%6,%7}, {%8,%9}, {%0,%1,%2,%3};"
        : "+f"(c[0]),"+f"(c[1]),"+f"(c[2]),"+f"(c[3])
        : "r"(a[0]),"r"(a[1]),"r"(a[2]),"r"(a[3]), "r"(b[0]),"r"(b[1]));
}
// A frag (m16k16) from K-major [row][32cols fp16] SW64 region (64B rows)
__device__ __forceinline__ void ld_afrag(uint32_t* r, uint32_t region, int mbase, int ks, int lane){
    int i = lane>>3, lm = lane&7;
    int row = mbase + lm + (i&1)*8;
    int kb  = ks*32 + (i>>1)*16;
    ldm_x4(r, region + swz64((uint32_t)(row*64 + kb)));
}
// B frags (two n8 x k16); r0=n0k0,r1=n0k8,r2=n8k0,r3=n8k8
__device__ __forceinline__ void ld_bfrag(uint32_t* r, uint32_t region, int nbase, int ks, int lane){
    int i = lane>>3, lm = lane&7;
    int row = nbase + lm + (i>>1)*8;
    int kb  = ks*32 + (i&1)*16;
    ldm_x4(r, region + swz64((uint32_t)(row*64 + kb)));
}

// ---------------- prep: x fp32 -> fp16 hi/lo ----------------
__global__ void prep_x(const float* __restrict__ x){
    size_t i = (size_t)blockIdx.x*256 + threadIdx.x;   // float4 index, 2097152 total
    float4 v = ((const float4*)x)[i];
    unsigned short h0,l0,h1,l1,h2,l2,h3,l3;
    h16split(v.x,h0,l0); h16split(v.y,h1,l1); h16split(v.z,h2,l2); h16split(v.w,h3,l3);
    uint2 hh = { (uint32_t)h0 | ((uint32_t)h1<<16), (uint32_t)h2 | ((uint32_t)h3<<16) };
    uint2 ll = { (uint32_t)l0 | ((uint32_t)l1<<16), (uint32_t)l2 | ((uint32_t)l3<<16) };
    ((uint2*)g_x_hi)[i] = hh;
    ((uint2*)g_x_lo)[i] = ll;
}

// ---------------- prep: weights -> pre-swizzled fp16 B tiles ----------------
// tile = (conv*3 + k)*8 + dchunk : 256 rows(f) x 32 cols(d), K-major, SW64 (16KB each)
__global__ void prep_w(const float* __restrict__ w1, const float* __restrict__ w2){
    int i = blockIdx.x*256 + threadIdx.x;              // 0..393215
    int kk = i % 3; int t = i / 3;
    int d = t & 255; int f = (t >> 8) & 255; int cv = t >> 16;
    const float* w = cv ? w2 : w1;
    float v = w[f*768 + d*3 + kk];
    __half hb = __float2half_rn(v);
    int tile = (cv*3 + kk)*8 + (d >> 5);
    uint32_t off = swz64((uint32_t)(f*64 + (d & 31)*2));
    *(unsigned short*)(g_wB_hi + (size_t)tile*16384 + off) = h_bits(hb);
}

// ---------------- fused conv+bias+relu+LN (+linear head) on mma.sync fp16 ----------------
// Tile: M=64 seq rows x N=256 filters, 256 threads, 2 CTAs/SM.
// MODE 0: reads g_x, writes g_h1 (fp16 hi/lo).  MODE 1: reads g_h1, writes log_dur.
template<int MODE>
__global__ void __launch_bounds__(256, 2)
conv_mma_kernel(const float* __restrict__ cb, const float* __restrict__ lg,
                const float* __restrict__ lb, const float* __restrict__ lw,
                const float* __restrict__ lbb,
                float* __restrict__ out_logdur)
{
    extern __shared__ __align__(1024) unsigned char dyn[];
    const int tid  = threadIdx.x;
    const int wid  = tid >> 5;
    const int lane = tid & 31;
    const int b    = blockIdx.x >> 4;
    const int s0   = (blockIdx.x & 15) * 64;
    const uint32_t sb = s2u(dyn);
    const int wm = wid >> 2, wn = wid & 3;          // warp tile: 32(M) x 64(N)
    const int l4 = lane & 3, lq = lane >> 2;

    float* p_bias = (float*)(dyn + PARAM_OFF);
    float* p_g    = p_bias + 256;
    float* p_b2   = p_g + 256;
    float* p_lw   = p_b2 + 256;
    p_bias[tid] = cb[tid]; p_g[tid] = lg[tid]; p_b2[tid] = lb[tid];
    if (MODE == 1) p_lw[tid] = lw[tid];

    const uint32_t* g_ah = MODE ? g_h1_hi : g_x_hi;
    const uint32_t* g_al = MODE ? g_h1_lo : g_x_lo;

    // ---- staging (cp.async); chunk = 32 K-cols ----
    // buf layout: aHi 0 | aLo 4096 | bHi 8192
    auto stage = [&](int c){
        const int buf = c & 1, kk = c >> 3, dc = c & 7, d0 = dc * 32;
        const uint32_t bufb = sb + buf*BUF_SZ;
        const int tile = MODE*24 + kk*8 + dc;
        const char* shi = (const char*)g_wB_hi + (size_t)tile*16384;
#pragma unroll
        for (int i = 0; i < 4; i++){
            uint32_t o = (uint32_t)(tid + i*256) << 4;
            cpa16(bufb + 8192 + o, shi + o);
        }
        // A: 64 rows x 32 cols; thread tid -> row tid>>2, 16B quadrant tid&3
        {
            int r = tid >> 2, q = tid & 3;
            int s = s0 + r + kk - 1;
            int valid = ((unsigned)s < (unsigned)S);
            size_t eoff = (((size_t)(b*S + (valid ? s : 0))*256 + d0 + q*8)) << 1;  // bytes
            uint32_t doff = swz64((uint32_t)(r*64 + q*16));
            cpa16z(bufb + doff,        (const char*)g_ah + eoff, valid);
            cpa16z(bufb + 4096 + doff, (const char*)g_al + eoff, valid);
        }
    };

    float acc[2][4][2][4];
#pragma unroll
    for (int mt=0;mt<2;mt++)
#pragma unroll
        for (int np=0;np<4;np++)
#pragma unroll
            for (int h=0;h<2;h++)
#pragma unroll
                for (int e=0;e<4;e++) acc[mt][np][h][e] = 0.f;

    stage(0); cpa_commit();

    for (int c = 0; c < NCHUNK; c++){
        if (c + 1 < NCHUNK){ stage(c+1); cpa_commit(); cpa_wait<1>(); }
        else cpa_wait<0>();
        __syncthreads();

        const uint32_t rAh = sb + (c&1)*BUF_SZ;
        const uint32_t rAl = rAh + 4096;
        const uint32_t rBh = rAh + 8192;

#pragma unroll
        for (int ks = 0; ks < 2; ks++){
            uint32_t aR[2][4], bH[4][4];
#pragma unroll
            for (int mt=0;mt<2;mt++) ld_afrag(aR[mt], rAh, wm*32+mt*16, ks, lane);
#pragma unroll
            for (int np=0;np<4;np++) ld_bfrag(bH[np], rBh, wn*64+np*16, ks, lane);
            // pass 1: Ah*Bh
#pragma unroll
            for (int mt=0;mt<2;mt++)
#pragma unroll
                for (int np=0;np<4;np++){
                    mma_f16(acc[mt][np][0], aR[mt], &bH[np][0]);
                    mma_f16(acc[mt][np][1], aR[mt], &bH[np][2]);
                }
            // pass 2: Al*Bh (A-lo reuses aR registers)
#pragma unroll
            for (int mt=0;mt<2;mt++) ld_afrag(aR[mt], rAl, wm*32+mt*16, ks, lane);
#pragma unroll
            for (int mt=0;mt<2;mt++)
#pragma unroll
                for (int np=0;np<4;np++){
                    mma_f16(acc[mt][np][0], aR[mt], &bH[np][0]);
                    mma_f16(acc[mt][np][1], aR[mt], &bH[np][2]);
                }
        }
        __syncthreads();
    }

    // ---------------- epilogue: bias+relu+LN (+linear) ----------------
    float* redS = (float*)dyn;           // [64][4]
    float* redQ = redS + 256;            // [64][4]
    float* s_mu = redQ + 256;            // [64]
    float* s_rs = s_mu + 64;             // [64]

#pragma unroll
    for (int mt=0;mt<2;mt++)
#pragma unroll
        for (int rh=0;rh<2;rh++){
            float sm_=0.f, sq_=0.f;
#pragma unroll
            for (int np=0;np<4;np++)
#pragma unroll
                for (int h=0;h<2;h++){
                    int cb_ = wn*64 + np*16 + h*8 + l4*2;
#pragma unroll
                    for (int e=0;e<2;e++){
                        float v = fmaxf(acc[mt][np][h][rh*2+e] + p_bias[cb_+e], 0.f);
                        sm_ += v; sq_ += v*v;
                    }
                }
            sm_ += __shfl_xor_sync(0xffffffffu, sm_, 1);
            sm_ += __shfl_xor_sync(0xffffffffu, sm_, 2);
            sq_ += __shfl_xor_sync(0xffffffffu, sq_, 1);
            sq_ += __shfl_xor_sync(0xffffffffu, sq_, 2);
            if (l4 == 0){
                int row = wm*32 + mt*16 + lq + rh*8;
                redS[row*4 + wn] = sm_;
                redQ[row*4 + wn] = sq_;
            }
        }
    __syncthreads();
    if (tid < 64){
        float sm_ = redS[tid*4]+redS[tid*4+1]+redS[tid*4+2]+redS[tid*4+3];
        float sq_ = redQ[tid*4]+redQ[tid*4+1]+redQ[tid*4+2]+redQ[tid*4+3];
        float mu  = sm_ * (1.f/256.f);
        s_mu[tid] = mu;
        s_rs[tid] = rsqrtf(sq_ * (1.f/256.f) - mu*mu + 1e-5f);
    }
    __syncthreads();

    if (MODE == 0){
#pragma unroll
        for (int mt=0;mt<2;mt++)
#pragma unroll
            for (int np=0;np<4;np++)
#pragma unroll
                for (int h=0;h<2;h++){
                    int cb_ = wn*64 + np*16 + h*8 + l4*2;
                    float g0 = p_g[cb_], g1 = p_g[cb_+1];
                    float o0 = p_b2[cb_], o1 = p_b2[cb_+1];
                    float bb0 = p_bias[cb_], bb1 = p_bias[cb_+1];
#pragma unroll
                    for (int rh=0;rh<2;rh++){
                        int row = wm*32 + mt*16 + lq + rh*8;
                        float mu = s_mu[row], rs = s_rs[row];
                        float y0 = (fmaxf(acc[mt][np][h][rh*2+0]+bb0,0.f)-mu)*rs*g0 + o0;
                        float y1 = (fmaxf(acc[mt][np][h][rh*2+1]+bb1,0.f)-mu)*rs*g1 + o1;
                        unsigned short h0,l0,h1,l1;
                        h16split(y0,h0,l0); h16split(y1,h1,l1);
                        size_t rg = (size_t)(b*S + s0 + row)*128 + (cb_>>1);
                        g_h1_hi[rg] = (uint32_t)h0 | ((uint32_t)h1<<16);
                        g_h1_lo[rg] = (uint32_t)l0 | ((uint32_t)l1<<16);
                    }
                }
    } else {
#pragma unroll
        for (int mt=0;mt<2;mt++)
#pragma unroll
            for (int rh=0;rh<2;rh++){
                int row = wm*32 + mt*16 + lq + rh*8;
                float mu = s_mu[row], rs = s_rs[row];
                float dt = 0.f;
#pragma unroll
                for (int np=0;np<4;np++)
#pragma unroll
                    for (int h=0;h<2;h++){
                        int cb_ = wn*64 + np*16 + h*8 + l4*2;
#pragma unroll
                        for (int e=0;e<2;e++){
                            float y = (fmaxf(acc[mt][np][h][rh*2+e]+p_bias[cb_+e],0.f)-mu)*rs*p_g[cb_+e] + p_b2[cb_+e];
                            dt += y * p_lw[cb_+e];
                        }
                    }
                dt += __shfl_xor_sync(0xffffffffu, dt, 1);
                dt += __shfl_xor_sync(0xffffffffu, dt, 2);
                if (l4 == 0) redS[row*4 + wn] = dt;
            }
        __syncthreads();
        if (tid < 64){
            float d = redS[tid*4]+redS[tid*4+1]+redS[tid*4+2]+redS[tid*4+3];
            out_logdur[(size_t)b*S + s0 + tid] = d + lbb[0];
        }
    }
}

// ---------------- scan: per-row cumsum, dur-as-float, mel_len ----------------
__global__ void scan_kernel(const int* __restrict__ dur,
                            const int* __restrict__ maxlen_p,
                            float* __restrict__ out_dur,
                            float* __restrict__ out_mel)
{
    __shared__ int sa[S];
    const int b = blockIdx.x, tid = threadIdx.x;   // 1024 threads
    int v = dur[b*S + tid];
    out_dur[b*S + tid] = (float)v;
    sa[tid] = v;
    __syncthreads();
    for (int off = 1; off < S; off <<= 1) {
        int t = sa[tid];
        int u = (tid >= off) ? sa[tid - off] : 0;
        __syncthreads();
        sa[tid] = t + u;
        __syncthreads();
    }
    g_cum[b*S + tid] = sa[tid];
    if (tid == S - 1) out_mel[b] = (float)min(sa[tid], maxlen_p[0]);
}

// ---------------- length regulator gather ----------------
__global__ void __launch_bounds__(256)
gather_kernel(const float* __restrict__ x,
              const int* __restrict__ maxlen_p,
              float* __restrict__ out)
{
    __shared__ int cum[S];
    __shared__ int srcs[TT];
    const int b  = blockIdx.x / (T / TT);
    const int t0 = (blockIdx.x % (T / TT)) * TT;
    const int tid = threadIdx.x;
    for (int i = tid; i < S; i += 256) cum[i] = g_cum[b*S + i];
    __syncthreads();
    const int mel = min(cum[S-1], maxlen_p[0]);
    if (tid < TT) {
        int t = t0 + tid;
        int lo = 0, hi = S;
        while (lo < hi) {
            int mid = (lo + hi) >> 1;
            if (cum[mid] <= t) lo = mid + 1; else hi = mid;
        }
        srcs[tid] = min(lo, S - 1);
    }
    __syncthreads();
    const int wi = tid >> 5, lane = tid & 31;
    const float4* __restrict__ x4 = (const float4*)x;
    float4* __restrict__ o4 = (float4*)out;
    for (int r = wi; r < TT; r += 8) {
        int t = t0 + r;
        float4* dst = o4 + ((size_t)b*T + t) * (D/4);
        if (t < mel) {
            const float4* src = x4 + ((size_t)b*S + srcs[r]) * (D/4);
            dst[lane]      = src[lane];
            dst[lane + 32] = src[lane + 32];
        } else {
            float4 z = make_float4(0.f,0.f,0.f,0.f);
            dst[lane]      = z;
            dst[lane + 32] = z;
        }
    }
}

extern "C" void kernel_launch(void* const* d_in, const int* in_sizes, int n_in,
                              void* d_out, int out_size)
{
    const float* x        = (const float*)d_in[0];
    const int*   duration = (const int*)d_in[2];
    const int*   maxlen   = (const int*)d_in[3];
    const float* w1  = (const float*)d_in[4];
    const float* b1  = (const float*)d_in[5];
    const float* g1  = (const float*)d_in[6];
    const float* be1 = (const float*)d_in[7];
    const float* w2  = (const float*)d_in[8];
    const float* b2  = (const float*)d_in[9];
    const float* g2  = (const float*)d_in[10];
    const float* be2 = (const float*)d_in[11];
    const float* lw  = (const float*)d_in[12];
    const float* lbb = (const float*)d_in[13];

    float* out        = (float*)d_out;
    float* out_logdur = out + (size_t)B*T*D;
    float* out_dur    = out_logdur + (size_t)B*S;
    float* out_mel    = out_dur + (size_t)B*S;

    static int s_init = 0;
    static cudaStream_t s_main = nullptr, s_side = nullptr;
    static cudaEvent_t evF = nullptr, evM = nullptr, evS = nullptr, evW = nullptr;
    if (!s_init) {
        cudaFuncSetAttribute(conv_mma_kernel<0>, cudaFuncAttributeMaxDynamicSharedMemorySize, SMEM_TOTAL);
        cudaFuncSetAttribute(conv_mma_kernel<1>, cudaFuncAttributeMaxDynamicSharedMemorySize, SMEM_TOTAL);
        bool ok = cudaStreamCreateWithFlags(&s_main, cudaStreamNonBlocking) == cudaSuccess &&
                  cudaStreamCreateWithFlags(&s_side, cudaStreamNonBlocking) == cudaSuccess &&
                  cudaEventCreateWithFlags(&evF, cudaEventDisableTiming) == cudaSuccess &&
                  cudaEventCreateWithFlags(&evM, cudaEventDisableTiming) == cudaSuccess &&
                  cudaEventCreateWithFlags(&evS, cudaEventDisableTiming) == cudaSuccess &&
                  cudaEventCreateWithFlags(&evW, cudaEventDisableTiming) == cudaSuccess;
        if (!ok) { s_main = nullptr; s_side = nullptr; }
        s_init = 1;
    }

    if (s_main) {
        // Fork both branches off the capture-origin stream; keep origin empty.
        cudaEventRecord(evF, 0);
        cudaStreamWaitEvent(s_main, evF, 0);
        cudaStreamWaitEvent(s_side, evF, 0);

        // Side branch: prep_w, then scan + gather (hide under convs)
        prep_w<<<1536, 256, 0, s_side>>>(w1, w2);
        cudaEventRecord(evW, s_side);
        scan_kernel<<<B, 1024, 0, s_side>>>(duration, maxlen, out_dur, out_mel);
        gather_kernel<<<B*(T/TT), 256, 0, s_side>>>(x, maxlen, out);
        cudaEventRecord(evS, s_side);

        // Main branch: prep_x, then conv chain
        prep_x<<<8192, 256, 0, s_main>>>(x);
        cudaStreamWaitEvent(s_main, evW, 0);
        conv_mma_kernel<0><<<512, 256, SMEM_TOTAL, s_main>>>(b1, g1, be1, nullptr, nullptr, nullptr);
        conv_mma_kernel<1><<<512, 256, SMEM_TOTAL, s_main>>>(b2, g2, be2, lw, lbb, out_logdur);
        cudaEventRecord(evM, s_main);

        cudaStreamWaitEvent(0, evS, 0);
        cudaStreamWaitEvent(0, evM, 0);
    } else {
        prep_x<<<8192, 256>>>(x);
        prep_w<<<1536, 256>>>(w1, w2);
        conv_mma_kernel<0><<<512, 256, SMEM_TOTAL>>>(b1, g1, be1, nullptr, nullptr, nullptr);
        conv_mma_kernel<1><<<512, 256, SMEM_TOTAL>>>(b2, g2, be2, lw, lbb, out_logdur);
        scan_kernel<<<B, 1024>>>(duration, maxlen, out_dur, out_mel);
        gather_kernel<<<B*(T/TT), 256>>>(x, maxlen, out);
    }
}

// round 10
// speedup vs baseline: 3.6900x; 1.0312x over previous
#include <cuda_runtime.h>
#include <cuda_fp16.h>
#include <cstdint>
#include <cstddef>
#include <cstring>

constexpr int B = 32, S = 1024, D = 256, F = 256, T = 8192;
constexpr int NCHUNK = 12;       // 3 k-shifts * 4 d-chunks of 64
constexpr int TT = 32;           // gather rows per block

// dynamic smem (bytes): two 48KB chunk buffers + 4KB params
// buf: aHi 8K | aLo 8K | bHi 32K
constexpr int BUF_SZ    = 49152;
constexpr int PARAM_OFF = 98304;
constexpr int SMEM_TOTAL = 102400;

// ---------------- device scratch (no allocation allowed) ----------------
__device__ __align__(16) uint32_t g_h1_hi[(size_t)B*S*128];   // fp16 pairs
__device__ __align__(16) uint32_t g_h1_lo[(size_t)B*S*128];
__device__ __align__(16) uint32_t g_x_hi[(size_t)B*S*128];
__device__ __align__(16) uint32_t g_x_lo[(size_t)B*S*128];
__device__ __align__(16) unsigned char g_wB_hi[2*12*32768];   // pre-swizzled fp16 B tiles (SW128)
__device__ int g_cum[B*S];

// ---------------- helpers ----------------
__device__ __forceinline__ uint32_t swz128(uint32_t off){ return off ^ ((off>>3)&0x70); }
__device__ __forceinline__ uint32_t s2u(const void* p){
    uint32_t a; asm("{ .reg .u64 t; cvta.to.shared.u64 t, %1; cvt.u32.u64 %0, t; }" : "=r"(a) : "l"(p)); return a;
}
__device__ __forceinline__ unsigned short h_bits(__half h){ unsigned short u; memcpy(&u,&h,2); return u; }
__device__ __forceinline__ void h16split(float v, unsigned short& h, unsigned short& l){
    __half hb = __float2half_rn(v);
    float r = v - __half2float(hb);
    __half lb = __float2half_rn(r);
    h = h_bits(hb); l = h_bits(lb);
}

__device__ __forceinline__ void cpa16(uint32_t dst, const void* src){
    asm volatile("cp.async.cg.shared.global [%0], [%1], 16;" :: "r"(dst), "l"(src) : "memory");
}
__device__ __forceinline__ void cpa16z(uint32_t dst, const void* src, int valid){
    int sz = valid ? 16 : 0;
    asm volatile("cp.async.cg.shared.global [%0], [%1], 16, %2;" :: "r"(dst), "l"(src), "r"(sz) : "memory");
}
__device__ __forceinline__ void cpa_commit(){ asm volatile("cp.async.commit_group;" ::: "memory"); }
template<int N> __device__ __forceinline__ void cpa_wait(){ asm volatile("cp.async.wait_group %0;" :: "n"(N) : "memory"); }

__device__ __forceinline__ void ldm_x4(uint32_t* r, uint32_t addr){
    asm volatile("ldmatrix.sync.aligned.m8n8.x4.shared.b16 {%0,%1,%2,%3}, [%4];"
        : "=r"(r[0]),"=r"(r[1]),"=r"(r[2]),"=r"(r[3]) : "r"(addr));
}
__device__ __forceinline__ void mma_f16(float* c, const uint32_t* a, const uint32_t* b){
    asm volatile("mma.sync.aligned.m16n8k16.row.col.f32.f16.f16.f32 "
        "{%0,%1,%2,%3}, {%4,%5,%6,%7}, {%8,%9}, {%0,%1,%2,%3};"
        : "+f"(c[0]),"+f"(c[1]),"+f"(c[2]),"+f"(c[3])
        : "r"(a[0]),"r"(a[1]),"r"(a[2]),"r"(a[3]), "r"(b[0]),"r"(b[1]));
}
// A frag (m16k16) from K-major [row][64cols fp16] SW128 region (128B rows)
__device__ __forceinline__ void ld_afrag(uint32_t* r, uint32_t region, int mbase, int ks, int lane){
    int i = lane>>3, lm = lane&7;
    int row = mbase + lm + (i&1)*8;
    int kb  = ks*32 + (i>>1)*16;
    ldm_x4(r, region + swz128((uint32_t)(row*128 + kb)));
}
// B frags (two n8 x k16); r0=n0k0,r1=n0k8,r2=n8k0,r3=n8k8
__device__ __forceinline__ void ld_bfrag(uint32_t* r, uint32_t region, int nbase, int ks, int lane){
    int i = lane>>3, lm = lane&7;
    int row = nbase + lm + (i>>1)*8;
    int kb  = ks*32 + (i&1)*16;
    ldm_x4(r, region + swz128((uint32_t)(row*128 + kb)));
}

// ---------------- prep: x fp32 -> fp16 hi/lo ----------------
__global__ void prep_x(const float* __restrict__ x){
    size_t i = (size_t)blockIdx.x*256 + threadIdx.x;   // float4 index, 2097152 total
    float4 v = ((const float4*)x)[i];
    unsigned short h0,l0,h1,l1,h2,l2,h3,l3;
    h16split(v.x,h0,l0); h16split(v.y,h1,l1); h16split(v.z,h2,l2); h16split(v.w,h3,l3);
    uint2 hh = { (uint32_t)h0 | ((uint32_t)h1<<16), (uint32_t)h2 | ((uint32_t)h3<<16) };
    uint2 ll = { (uint32_t)l0 | ((uint32_t)l1<<16), (uint32_t)l2 | ((uint32_t)l3<<16) };
    ((uint2*)g_x_hi)[i] = hh;
    ((uint2*)g_x_lo)[i] = ll;
}

// ---------------- prep: weights -> pre-swizzled fp16 B tiles ----------------
// tile = (conv*3 + k)*4 + dchunk : 256 rows(f) x 64 cols(d), K-major, SW128 (32KB each)
__global__ void prep_w(const float* __restrict__ w1, const float* __restrict__ w2){
    int i = blockIdx.x*256 + threadIdx.x;              // 0..393215
    int kk = i % 3; int t = i / 3;
    int d = t & 255; int f = (t >> 8) & 255; int cv = t >> 16;
    const float* w = cv ? w2 : w1;
    float v = w[f*768 + d*3 + kk];
    __half hb = __float2half_rn(v);
    int tile = (cv*3 + kk)*4 + (d >> 6);
    uint32_t off = swz128((uint32_t)(f*128 + (d & 63)*2));
    *(unsigned short*)(g_wB_hi + (size_t)tile*32768 + off) = h_bits(hb);
}

// ---------------- fused conv+bias+relu+LN (+linear head) on mma.sync fp16 ----------------
// Tile: M=64 seq rows x N=256 filters, 256 threads, 2 CTAs/SM. Grid 256 per batch-half.
// MODE 0: reads g_x, writes g_h1 (fp16 hi/lo).  MODE 1: reads g_h1, writes log_dur.
template<int MODE>
__global__ void __launch_bounds__(256, 2)
conv_mma_kernel(const float* __restrict__ cb, const float* __restrict__ lg,
                const float* __restrict__ lb, const float* __restrict__ lw,
                const float* __restrict__ lbb,
                float* __restrict__ out_logdur, int b0)
{
    extern __shared__ __align__(1024) unsigned char dyn[];
    const int tid  = threadIdx.x;
    const int wid  = tid >> 5;
    const int lane = tid & 31;
    const int b    = b0 + (blockIdx.x >> 4);
    const int s0   = (blockIdx.x & 15) * 64;
    const uint32_t sb = s2u(dyn);
    const int wm = wid >> 2, wn = wid & 3;          // warp tile: 32(M) x 64(N)
    const int l4 = lane & 3, lq = lane >> 2;

    float* p_bias = (float*)(dyn + PARAM_OFF);
    float* p_g    = p_bias + 256;
    float* p_b2   = p_g + 256;
    float* p_lw   = p_b2 + 256;
    p_bias[tid] = cb[tid]; p_g[tid] = lg[tid]; p_b2[tid] = lb[tid];
    if (MODE == 1) p_lw[tid] = lw[tid];

    const uint32_t* g_ah = MODE ? g_h1_hi : g_x_hi;
    const uint32_t* g_al = MODE ? g_h1_lo : g_x_lo;

    // ---- staging (cp.async); chunk = 64 K-cols ----
    // buf layout: aHi 0 | aLo 8192 | bHi 16384
    auto stage = [&](int c){
        const int buf = c & 1, kk = c >> 2, dc = c & 3, d0 = dc * 64;
        const uint32_t bufb = sb + buf*BUF_SZ;
        const int tile = MODE*12 + kk*4 + dc;
        const char* shi = (const char*)g_wB_hi + (size_t)tile*32768;
#pragma unroll
        for (int i = 0; i < 8; i++){
            uint32_t o = (uint32_t)(tid + i*256) << 4;
            cpa16(bufb + 16384 + o, shi + o);
        }
        // A: 64 rows x 64 cols; slot -> row slot>>3, 16B quadrant slot&7
#pragma unroll
        for (int i = 0; i < 2; i++){
            int slot = tid + i*256;
            int r = slot >> 3, q = slot & 7;
            int s = s0 + r + kk - 1;
            int valid = ((unsigned)s < (unsigned)S);
            size_t eoff = (((size_t)(b*S + (valid ? s : 0))*256 + d0 + q*8)) << 1;  // bytes
            uint32_t doff = swz128((uint32_t)(r*128 + q*16));
            cpa16z(bufb + doff,        (const char*)g_ah + eoff, valid);
            cpa16z(bufb + 8192 + doff, (const char*)g_al + eoff, valid);
        }
    };

    float acc[2][4][2][4];
#pragma unroll
    for (int mt=0;mt<2;mt++)
#pragma unroll
        for (int np=0;np<4;np++)
#pragma unroll
            for (int h=0;h<2;h++)
#pragma unroll
                for (int e=0;e<4;e++) acc[mt][np][h][e] = 0.f;

    stage(0); cpa_commit();

    for (int c = 0; c < NCHUNK; c++){
        if (c + 1 < NCHUNK){ stage(c+1); cpa_commit(); cpa_wait<1>(); }
        else cpa_wait<0>();
        __syncthreads();

        const uint32_t rAh = sb + (c&1)*BUF_SZ;
        const uint32_t rAl = rAh + 8192;
        const uint32_t rBh = rAh + 16384;

#pragma unroll
        for (int ks = 0; ks < 4; ks++){
            uint32_t aR[2][4], bH[4][4];
#pragma unroll
            for (int mt=0;mt<2;mt++) ld_afrag(aR[mt], rAh, wm*32+mt*16, ks, lane);
#pragma unroll
            for (int np=0;np<4;np++) ld_bfrag(bH[np], rBh, wn*64+np*16, ks, lane);
            // pass 1: Ah*Bh
#pragma unroll
            for (int mt=0;mt<2;mt++)
#pragma unroll
                for (int np=0;np<4;np++){
                    mma_f16(acc[mt][np][0], aR[mt], &bH[np][0]);
                    mma_f16(acc[mt][np][1], aR[mt], &bH[np][2]);
                }
            // pass 2: Al*Bh (A-lo reuses aR registers)
#pragma unroll
            for (int mt=0;mt<2;mt++) ld_afrag(aR[mt], rAl, wm*32+mt*16, ks, lane);
#pragma unroll
            for (int mt=0;mt<2;mt++)
#pragma unroll
                for (int np=0;np<4;np++){
                    mma_f16(acc[mt][np][0], aR[mt], &bH[np][0]);
                    mma_f16(acc[mt][np][1], aR[mt], &bH[np][2]);
                }
        }
        __syncthreads();
    }

    // ---------------- epilogue: bias+relu+LN (+linear) ----------------
    float* redS = (float*)dyn;           // [64][4]
    float* redQ = redS + 256;            // [64][4]
    float* s_mu = redQ + 256;            // [64]
    float* s_rs = s_mu + 64;             // [64]

#pragma unroll
    for (int mt=0;mt<2;mt++)
#pragma unroll
        for (int rh=0;rh<2;rh++){
            float sm_=0.f, sq_=0.f;
#pragma unroll
            for (int np=0;np<4;np++)
#pragma unroll
                for (int h=0;h<2;h++){
                    int cb_ = wn*64 + np*16 + h*8 + l4*2;
#pragma unroll
                    for (int e=0;e<2;e++){
                        float v = fmaxf(acc[mt][np][h][rh*2+e] + p_bias[cb_+e], 0.f);
                        sm_ += v; sq_ += v*v;
                    }
                }
            sm_ += __shfl_xor_sync(0xffffffffu, sm_, 1);
            sm_ += __shfl_xor_sync(0xffffffffu, sm_, 2);
            sq_ += __shfl_xor_sync(0xffffffffu, sq_, 1);
            sq_ += __shfl_xor_sync(0xffffffffu, sq_, 2);
            if (l4 == 0){
                int row = wm*32 + mt*16 + lq + rh*8;
                redS[row*4 + wn] = sm_;
                redQ[row*4 + wn] = sq_;
            }
        }
    __syncthreads();
    if (tid < 64){
        float sm_ = redS[tid*4]+redS[tid*4+1]+redS[tid*4+2]+redS[tid*4+3];
        float sq_ = redQ[tid*4]+redQ[tid*4+1]+redQ[tid*4+2]+redQ[tid*4+3];
        float mu  = sm_ * (1.f/256.f);
        s_mu[tid] = mu;
        s_rs[tid] = rsqrtf(sq_ * (1.f/256.f) - mu*mu + 1e-5f);
    }
    __syncthreads();

    if (MODE == 0){
#pragma unroll
        for (int mt=0;mt<2;mt++)
#pragma unroll
            for (int np=0;np<4;np++)
#pragma unroll
                for (int h=0;h<2;h++){
                    int cb_ = wn*64 + np*16 + h*8 + l4*2;
                    float g0 = p_g[cb_], g1 = p_g[cb_+1];
                    float o0 = p_b2[cb_], o1 = p_b2[cb_+1];
                    float bb0 = p_bias[cb_], bb1 = p_bias[cb_+1];
#pragma unroll
                    for (int rh=0;rh<2;rh++){
                        int row = wm*32 + mt*16 + lq + rh*8;
                        float mu = s_mu[row], rs = s_rs[row];
                        float y0 = (fmaxf(acc[mt][np][h][rh*2+0]+bb0,0.f)-mu)*rs*g0 + o0;
                        float y1 = (fmaxf(acc[mt][np][h][rh*2+1]+bb1,0.f)-mu)*rs*g1 + o1;
                        unsigned short h0,l0,h1,l1;
                        h16split(y0,h0,l0); h16split(y1,h1,l1);
                        size_t rg = (size_t)(b*S + s0 + row)*128 + (cb_>>1);
                        g_h1_hi[rg] = (uint32_t)h0 | ((uint32_t)h1<<16);
                        g_h1_lo[rg] = (uint32_t)l0 | ((uint32_t)l1<<16);
                    }
                }
    } else {
#pragma unroll
        for (int mt=0;mt<2;mt++)
#pragma unroll
            for (int rh=0;rh<2;rh++){
                int row = wm*32 + mt*16 + lq + rh*8;
                float mu = s_mu[row], rs = s_rs[row];
                float dt = 0.f;
#pragma unroll
                for (int np=0;np<4;np++)
#pragma unroll
                    for (int h=0;h<2;h++){
                        int cb_ = wn*64 + np*16 + h*8 + l4*2;
#pragma unroll
                        for (int e=0;e<2;e++){
                            float y = (fmaxf(acc[mt][np][h][rh*2+e]+p_bias[cb_+e],0.f)-mu)*rs*p_g[cb_+e] + p_b2[cb_+e];
                            dt += y * p_lw[cb_+e];
                        }
                    }
                dt += __shfl_xor_sync(0xffffffffu, dt, 1);
                dt += __shfl_xor_sync(0xffffffffu, dt, 2);
                if (l4 == 0) redS[row*4 + wn] = dt;
            }
        __syncthreads();
        if (tid < 64){
            float d = redS[tid*4]+redS[tid*4+1]+redS[tid*4+2]+redS[tid*4+3];
            out_logdur[(size_t)b*S + s0 + tid] = d + lbb[0];
        }
    }
}

// ---------------- scan: per-row cumsum, dur-as-float, mel_len ----------------
__global__ void scan_kernel(const int* __restrict__ dur,
                            const int* __restrict__ maxlen_p,
                            float* __restrict__ out_dur,
                            float* __restrict__ out_mel)
{
    __shared__ int sa[S];
    const int b = blockIdx.x, tid = threadIdx.x;   // 1024 threads
    int v = dur[b*S + tid];
    out_dur[b*S + tid] = (float)v;
    sa[tid] = v;
    __syncthreads();
    for (int off = 1; off < S; off <<= 1) {
        int t = sa[tid];
        int u = (tid >= off) ? sa[tid - off] : 0;
        __syncthreads();
        sa[tid] = t + u;
        __syncthreads();
    }
    g_cum[b*S + tid] = sa[tid];
    if (tid == S - 1) out_mel[b] = (float)min(sa[tid], maxlen_p[0]);
}

// ---------------- length regulator gather ----------------
__global__ void __launch_bounds__(256)
gather_kernel(const float* __restrict__ x,
              const int* __restrict__ maxlen_p,
              float* __restrict__ out)
{
    __shared__ int cum[S];
    __shared__ int srcs[TT];
    const int b  = blockIdx.x / (T / TT);
    const int t0 = (blockIdx.x % (T / TT)) * TT;
    const int tid = threadIdx.x;
    for (int i = tid; i < S; i += 256) cum[i] = g_cum[b*S + i];
    __syncthreads();
    const int mel = min(cum[S-1], maxlen_p[0]);
    if (tid < TT) {
        int t = t0 + tid;
        int lo = 0, hi = S;
        while (lo < hi) {
            int mid = (lo + hi) >> 1;
            if (cum[mid] <= t) lo = mid + 1; else hi = mid;
        }
        srcs[tid] = min(lo, S - 1);
    }
    __syncthreads();
    const int wi = tid >> 5, lane = tid & 31;
    const float4* __restrict__ x4 = (const float4*)x;
    float4* __restrict__ o4 = (float4*)out;
    for (int r = wi; r < TT; r += 8) {
        int t = t0 + r;
        float4* dst = o4 + ((size_t)b*T + t) * (D/4);
        if (t < mel) {
            const float4* src = x4 + ((size_t)b*S + srcs[r]) * (D/4);
            dst[lane]      = src[lane];
            dst[lane + 32] = src[lane + 32];
        } else {
            float4 z = make_float4(0.f,0.f,0.f,0.f);
            dst[lane]      = z;
            dst[lane + 32] = z;
        }
    }
}

extern "C" void kernel_launch(void* const* d_in, const int* in_sizes, int n_in,
                              void* d_out, int out_size)
{
    const float* x        = (const float*)d_in[0];
    const int*   duration = (const int*)d_in[2];
    const int*   maxlen   = (const int*)d_in[3];
    const float* w1  = (const float*)d_in[4];
    const float* b1  = (const float*)d_in[5];
    const float* g1  = (const float*)d_in[6];
    const float* be1 = (const float*)d_in[7];
    const float* w2  = (const float*)d_in[8];
    const float* b2  = (const float*)d_in[9];
    const float* g2  = (const float*)d_in[10];
    const float* be2 = (const float*)d_in[11];
    const float* lw  = (const float*)d_in[12];
    const float* lbb = (const float*)d_in[13];

    float* out        = (float*)d_out;
    float* out_logdur = out + (size_t)B*T*D;
    float* out_dur    = out_logdur + (size_t)B*S;
    float* out_mel    = out_dur + (size_t)B*S;

    static int s_init = 0;
    static cudaStream_t s_main = nullptr, s_side = nullptr;
    static cudaEvent_t evF = nullptr, evM = nullptr, evS = nullptr, evW = nullptr, ev01 = nullptr;
    if (!s_init) {
        cudaFuncSetAttribute(conv_mma_kernel<0>, cudaFuncAttributeMaxDynamicSharedMemorySize, SMEM_TOTAL);
        cudaFuncSetAttribute(conv_mma_kernel<1>, cudaFuncAttributeMaxDynamicSharedMemorySize, SMEM_TOTAL);
        bool ok = cudaStreamCreateWithFlags(&s_main, cudaStreamNonBlocking) == cudaSuccess &&
                  cudaStreamCreateWithFlags(&s_side, cudaStreamNonBlocking) == cudaSuccess &&
                  cudaEventCreateWithFlags(&evF, cudaEventDisableTiming) == cudaSuccess &&
                  cudaEventCreateWithFlags(&evM, cudaEventDisableTiming) == cudaSuccess &&
                  cudaEventCreateWithFlags(&evS, cudaEventDisableTiming) == cudaSuccess &&
                  cudaEventCreateWithFlags(&evW, cudaEventDisableTiming) == cudaSuccess &&
                  cudaEventCreateWithFlags(&ev01, cudaEventDisableTiming) == cudaSuccess;
        if (!ok) { s_main = nullptr; s_side = nullptr; }
        s_init = 1;
    }

    if (s_main) {
        // Fork both branches off the capture-origin stream; keep origin empty.
        // NOTE: in capture mode every cudaStreamWaitEvent must come AFTER (in
        // host issue order) the cudaEventRecord of that event.
        cudaEventRecord(evF, 0);
        cudaStreamWaitEvent(s_main, evF, 0);
        cudaStreamWaitEvent(s_side, evF, 0);

        // Side 1/2: weight prep
        prep_w<<<1536, 256, 0, s_side>>>(w1, w2);
        cudaEventRecord(evW, s_side);

        // Main 1/2: x prep, then conv0 first half; record ev01
        prep_x<<<8192, 256, 0, s_main>>>(x);
        cudaStreamWaitEvent(s_main, evW, 0);
        conv_mma_kernel<0><<<256, 256, SMEM_TOTAL, s_main>>>(b1, g1, be1, nullptr, nullptr, nullptr, 0);
        cudaEventRecord(ev01, s_main);

        // Side 2/2: scan + gather (hide under convs), then conv1 first half
        // (depends on conv0 first half; packs into conv0 second half's tail).
        scan_kernel<<<B, 1024, 0, s_side>>>(duration, maxlen, out_dur, out_mel);
        gather_kernel<<<B*(T/TT), 256, 0, s_side>>>(x, maxlen, out);
        cudaStreamWaitEvent(s_side, ev01, 0);
        conv_mma_kernel<1><<<256, 256, SMEM_TOTAL, s_side>>>(b2, g2, be2, lw, lbb, out_logdur, 0);
        cudaEventRecord(evS, s_side);

        // Main 2/2: conv0 second half, conv1 second half
        conv_mma_kernel<0><<<256, 256, SMEM_TOTAL, s_main>>>(b1, g1, be1, nullptr, nullptr, nullptr, 16);
        conv_mma_kernel<1><<<256, 256, SMEM_TOTAL, s_main>>>(b2, g2, be2, lw, lbb, out_logdur, 16);
        cudaEventRecord(evM, s_main);

        cudaStreamWaitEvent(0, evS, 0);
        cudaStreamWaitEvent(0, evM, 0);
    } else {
        prep_x<<<8192, 256>>>(x);
        prep_w<<<1536, 256>>>(w1, w2);
        conv_mma_kernel<0><<<256, 256, SMEM_TOTAL>>>(b1, g1, be1, nullptr, nullptr, nullptr, 0);
        conv_mma_kernel<0><<<256, 256, SMEM_TOTAL>>>(b1, g1, be1, nullptr, nullptr, nullptr, 16);
        conv_mma_kernel<1><<<256, 256, SMEM_TOTAL>>>(b2, g2, be2, lw, lbb, out_logdur, 0);
        conv_mma_kernel<1><<<256, 256, SMEM_TOTAL>>>(b2, g2, be2, lw, lbb, out_logdur, 16);
        scan_kernel<<<B, 1024>>>(duration, maxlen, out_dur, out_mel);
        gather_kernel<<<B*(T/TT), 256>>>(x, maxlen, out);
    }
}

// round 11
// speedup vs baseline: 3.9515x; 1.0709x over previous
#include <cuda_runtime.h>
#include <cuda_fp16.h>
#include <cstdint>
#include <cstddef>
#include <cstring>

constexpr int B = 32, S = 1024, D = 256, F = 256, T = 8192;
constexpr int NCHUNK = 12;       // 3 k-shifts * 4 d-chunks of 64
constexpr int TT = 32;           // gather rows per block

// dynamic smem (bytes): two 48KB chunk buffers + 4KB params
// buf: aHi 8K | aLo 8K | bHi 32K
constexpr int BUF_SZ    = 49152;
constexpr int PARAM_OFF = 98304;
constexpr int SMEM_TOTAL = 102400;

// ---------------- device scratch (no allocation allowed) ----------------
__device__ __align__(16) uint32_t g_h1_hi[(size_t)B*S*128];   // fp16 pairs
__device__ __align__(16) uint32_t g_h1_lo[(size_t)B*S*128];
__device__ __align__(16) uint32_t g_x_hi[(size_t)B*S*128];
__device__ __align__(16) uint32_t g_x_lo[(size_t)B*S*128];
__device__ __align__(16) unsigned char g_wB_hi[2*12*32768];   // pre-swizzled fp16 B tiles (SW128)
__device__ int g_cum[B*S];

// ---------------- helpers ----------------
__device__ __forceinline__ uint32_t swz128(uint32_t off){ return off ^ ((off>>3)&0x70); }
__device__ __forceinline__ uint32_t s2u(const void* p){
    uint32_t a; asm("{ .reg .u64 t; cvta.to.shared.u64 t, %1; cvt.u32.u64 %0, t; }" : "=r"(a) : "l"(p)); return a;
}
__device__ __forceinline__ unsigned short h_bits(__half h){ unsigned short u; memcpy(&u,&h,2); return u; }
__device__ __forceinline__ void h16split(float v, unsigned short& h, unsigned short& l){
    __half hb = __float2half_rn(v);
    float r = v - __half2float(hb);
    __half lb = __float2half_rn(r);
    h = h_bits(hb); l = h_bits(lb);
}

__device__ __forceinline__ void cpa16(uint32_t dst, const void* src){
    asm volatile("cp.async.cg.shared.global [%0], [%1], 16;" :: "r"(dst), "l"(src) : "memory");
}
__device__ __forceinline__ void cpa16z(uint32_t dst, const void* src, int valid){
    int sz = valid ? 16 : 0;
    asm volatile("cp.async.cg.shared.global [%0], [%1], 16, %2;" :: "r"(dst), "l"(src), "r"(sz) : "memory");
}
__device__ __forceinline__ void cpa_commit(){ asm volatile("cp.async.commit_group;" ::: "memory"); }
template<int N> __device__ __forceinline__ void cpa_wait(){ asm volatile("cp.async.wait_group %0;" :: "n"(N) : "memory"); }

__device__ __forceinline__ void ldm_x4(uint32_t* r, uint32_t addr){
    asm volatile("ldmatrix.sync.aligned.m8n8.x4.shared.b16 {%0,%1,%2,%3}, [%4];"
        : "=r"(r[0]),"=r"(r[1]),"=r"(r[2]),"=r"(r[3]) : "r"(addr));
}
__device__ __forceinline__ void mma_f16(float* c, const uint32_t* a, const uint32_t* b){
    asm volatile("mma.sync.aligned.m16n8k16.row.col.f32.f16.f16.f32 "
        "{%0,%1,%2,%3}, {%4,%5,%6,%7}, {%8,%9}, {%0,%1,%2,%3};"
        : "+f"(c[0]),"+f"(c[1]),"+f"(c[2]),"+f"(c[3])
        : "r"(a[0]),"r"(a[1]),"r"(a[2]),"r"(a[3]), "r"(b[0]),"r"(b[1]));
}
// A frag (m16k16) from K-major [row][64cols fp16] SW128 region (128B rows)
__device__ __forceinline__ void ld_afrag(uint32_t* r, uint32_t region, int mbase, int ks, int lane){
    int i = lane>>3, lm = lane&7;
    int row = mbase + lm + (i&1)*8;
    int kb  = ks*32 + (i>>1)*16;
    ldm_x4(r, region + swz128((uint32_t)(row*128 + kb)));
}
// B frags (two n8 x k16); r0=n0k0,r1=n0k8,r2=n8k0,r3=n8k8
__device__ __forceinline__ void ld_bfrag(uint32_t* r, uint32_t region, int nbase, int ks, int lane){
    int i = lane>>3, lm = lane&7;
    int row = nbase + lm + (i>>1)*8;
    int kb  = ks*32 + (i&1)*16;
    ldm_x4(r, region + swz128((uint32_t)(row*128 + kb)));
}

// ---------------- prep: x fp32 -> fp16 hi/lo (half-batch granular) ----------------
__global__ void prep_x(const float* __restrict__ x, int blk0){
    size_t i = (size_t)(blockIdx.x + blk0)*256 + threadIdx.x;   // float4 index
    float4 v = ((const float4*)x)[i];
    unsigned short h0,l0,h1,l1,h2,l2,h3,l3;
    h16split(v.x,h0,l0); h16split(v.y,h1,l1); h16split(v.z,h2,l2); h16split(v.w,h3,l3);
    uint2 hh = { (uint32_t)h0 | ((uint32_t)h1<<16), (uint32_t)h2 | ((uint32_t)h3<<16) };
    uint2 ll = { (uint32_t)l0 | ((uint32_t)l1<<16), (uint32_t)l2 | ((uint32_t)l3<<16) };
    ((uint2*)g_x_hi)[i] = hh;
    ((uint2*)g_x_lo)[i] = ll;
}

// ---------------- prep: weights -> pre-swizzled fp16 B tiles ----------------
// tile = (conv*3 + k)*4 + dchunk : 256 rows(f) x 64 cols(d), K-major, SW128 (32KB each)
__global__ void prep_w(const float* __restrict__ w1, const float* __restrict__ w2){
    int i = blockIdx.x*256 + threadIdx.x;              // 0..393215
    int kk = i % 3; int t = i / 3;
    int d = t & 255; int f = (t >> 8) & 255; int cv = t >> 16;
    const float* w = cv ? w2 : w1;
    float v = w[f*768 + d*3 + kk];
    __half hb = __float2half_rn(v);
    int tile = (cv*3 + kk)*4 + (d >> 6);
    uint32_t off = swz128((uint32_t)(f*128 + (d & 63)*2));
    *(unsigned short*)(g_wB_hi + (size_t)tile*32768 + off) = h_bits(hb);
}

// ---------------- fused conv+bias+relu+LN (+linear head) on mma.sync fp16 ----------------
// Tile: M=64 seq rows x N=256 filters, 256 threads, 2 CTAs/SM. Grid 256 per batch-half.
// MODE 0: reads g_x, writes g_h1 (fp16 hi/lo).  MODE 1: reads g_h1, writes log_dur.
template<int MODE>
__global__ void __launch_bounds__(256, 2)
conv_mma_kernel(const float* __restrict__ cb, const float* __restrict__ lg,
                const float* __restrict__ lb, const float* __restrict__ lw,
                const float* __restrict__ lbb,
                float* __restrict__ out_logdur, int b0)
{
    extern __shared__ __align__(1024) unsigned char dyn[];
    const int tid  = threadIdx.x;
    const int wid  = tid >> 5;
    const int lane = tid & 31;
    const int b    = b0 + (blockIdx.x >> 4);
    const int s0   = (blockIdx.x & 15) * 64;
    const uint32_t sb = s2u(dyn);
    const int wm = wid >> 2, wn = wid & 3;          // warp tile: 32(M) x 64(N)
    const int l4 = lane & 3, lq = lane >> 2;

    float* p_bias = (float*)(dyn + PARAM_OFF);
    float* p_g    = p_bias + 256;
    float* p_b2   = p_g + 256;
    float* p_lw   = p_b2 + 256;
    p_bias[tid] = cb[tid]; p_g[tid] = lg[tid]; p_b2[tid] = lb[tid];
    if (MODE == 1) p_lw[tid] = lw[tid];

    const uint32_t* g_ah = MODE ? g_h1_hi : g_x_hi;
    const uint32_t* g_al = MODE ? g_h1_lo : g_x_lo;

    // ---- staging (cp.async); chunk = 64 K-cols ----
    // buf layout: aHi 0 | aLo 8192 | bHi 16384
    auto stage = [&](int c){
        const int buf = c & 1, kk = c >> 2, dc = c & 3, d0 = dc * 64;
        const uint32_t bufb = sb + buf*BUF_SZ;
        const int tile = MODE*12 + kk*4 + dc;
        const char* shi = (const char*)g_wB_hi + (size_t)tile*32768;
#pragma unroll
        for (int i = 0; i < 8; i++){
            uint32_t o = (uint32_t)(tid + i*256) << 4;
            cpa16(bufb + 16384 + o, shi + o);
        }
        // A: 64 rows x 64 cols; slot -> row slot>>3, 16B quadrant slot&7
#pragma unroll
        for (int i = 0; i < 2; i++){
            int slot = tid + i*256;
            int r = slot >> 3, q = slot & 7;
            int s = s0 + r + kk - 1;
            int valid = ((unsigned)s < (unsigned)S);
            size_t eoff = (((size_t)(b*S + (valid ? s : 0))*256 + d0 + q*8)) << 1;  // bytes
            uint32_t doff = swz128((uint32_t)(r*128 + q*16));
            cpa16z(bufb + doff,        (const char*)g_ah + eoff, valid);
            cpa16z(bufb + 8192 + doff, (const char*)g_al + eoff, valid);
        }
    };

    float acc[2][4][2][4];
#pragma unroll
    for (int mt=0;mt<2;mt++)
#pragma unroll
        for (int np=0;np<4;np++)
#pragma unroll
            for (int h=0;h<2;h++)
#pragma unroll
                for (int e=0;e<4;e++) acc[mt][np][h][e] = 0.f;

    stage(0); cpa_commit();

    for (int c = 0; c < NCHUNK; c++){
        if (c + 1 < NCHUNK){ stage(c+1); cpa_commit(); cpa_wait<1>(); }
        else cpa_wait<0>();
        __syncthreads();

        const uint32_t rAh = sb + (c&1)*BUF_SZ;
        const uint32_t rAl = rAh + 8192;
        const uint32_t rBh = rAh + 16384;

#pragma unroll
        for (int ks = 0; ks < 4; ks++){
            uint32_t aR[2][4], bH[4][4];
#pragma unroll
            for (int mt=0;mt<2;mt++) ld_afrag(aR[mt], rAh, wm*32+mt*16, ks, lane);
#pragma unroll
            for (int np=0;np<4;np++) ld_bfrag(bH[np], rBh, wn*64+np*16, ks, lane);
            // pass 1: Ah*Bh
#pragma unroll
            for (int mt=0;mt<2;mt++)
#pragma unroll
                for (int np=0;np<4;np++){
                    mma_f16(acc[mt][np][0], aR[mt], &bH[np][0]);
                    mma_f16(acc[mt][np][1], aR[mt], &bH[np][2]);
                }
            // pass 2: Al*Bh (A-lo reuses aR registers)
#pragma unroll
            for (int mt=0;mt<2;mt++) ld_afrag(aR[mt], rAl, wm*32+mt*16, ks, lane);
#pragma unroll
            for (int mt=0;mt<2;mt++)
#pragma unroll
                for (int np=0;np<4;np++){
                    mma_f16(acc[mt][np][0], aR[mt], &bH[np][0]);
                    mma_f16(acc[mt][np][1], aR[mt], &bH[np][2]);
                }
        }
        __syncthreads();
    }

    // ---------------- epilogue: bias+relu+LN (+linear) ----------------
    float* redS = (float*)dyn;           // [64][4]
    float* redQ = redS + 256;            // [64][4]
    float* s_mu = redQ + 256;            // [64]
    float* s_rs = s_mu + 64;             // [64]

#pragma unroll
    for (int mt=0;mt<2;mt++)
#pragma unroll
        for (int rh=0;rh<2;rh++){
            float sm_=0.f, sq_=0.f;
#pragma unroll
            for (int np=0;np<4;np++)
#pragma unroll
                for (int h=0;h<2;h++){
                    int cb_ = wn*64 + np*16 + h*8 + l4*2;
#pragma unroll
                    for (int e=0;e<2;e++){
                        float v = fmaxf(acc[mt][np][h][rh*2+e] + p_bias[cb_+e], 0.f);
                        sm_ += v; sq_ += v*v;
                    }
                }
            sm_ += __shfl_xor_sync(0xffffffffu, sm_, 1);
            sm_ += __shfl_xor_sync(0xffffffffu, sm_, 2);
            sq_ += __shfl_xor_sync(0xffffffffu, sq_, 1);
            sq_ += __shfl_xor_sync(0xffffffffu, sq_, 2);
            if (l4 == 0){
                int row = wm*32 + mt*16 + lq + rh*8;
                redS[row*4 + wn] = sm_;
                redQ[row*4 + wn] = sq_;
            }
        }
    __syncthreads();
    if (tid < 64){
        float sm_ = redS[tid*4]+redS[tid*4+1]+redS[tid*4+2]+redS[tid*4+3];
        float sq_ = redQ[tid*4]+redQ[tid*4+1]+redQ[tid*4+2]+redQ[tid*4+3];
        float mu  = sm_ * (1.f/256.f);
        s_mu[tid] = mu;
        s_rs[tid] = rsqrtf(sq_ * (1.f/256.f) - mu*mu + 1e-5f);
    }
    __syncthreads();

    if (MODE == 0){
#pragma unroll
        for (int mt=0;mt<2;mt++)
#pragma unroll
            for (int np=0;np<4;np++)
#pragma unroll
                for (int h=0;h<2;h++){
                    int cb_ = wn*64 + np*16 + h*8 + l4*2;
                    float g0 = p_g[cb_], g1 = p_g[cb_+1];
                    float o0 = p_b2[cb_], o1 = p_b2[cb_+1];
                    float bb0 = p_bias[cb_], bb1 = p_bias[cb_+1];
#pragma unroll
                    for (int rh=0;rh<2;rh++){
                        int row = wm*32 + mt*16 + lq + rh*8;
                        float mu = s_mu[row], rs = s_rs[row];
                        float y0 = (fmaxf(acc[mt][np][h][rh*2+0]+bb0,0.f)-mu)*rs*g0 + o0;
                        float y1 = (fmaxf(acc[mt][np][h][rh*2+1]+bb1,0.f)-mu)*rs*g1 + o1;
                        unsigned short h0,l0,h1,l1;
                        h16split(y0,h0,l0); h16split(y1,h1,l1);
                        size_t rg = (size_t)(b*S + s0 + row)*128 + (cb_>>1);
                        g_h1_hi[rg] = (uint32_t)h0 | ((uint32_t)h1<<16);
                        g_h1_lo[rg] = (uint32_t)l0 | ((uint32_t)l1<<16);
                    }
                }
    } else {
#pragma unroll
        for (int mt=0;mt<2;mt++)
#pragma unroll
            for (int rh=0;rh<2;rh++){
                int row = wm*32 + mt*16 + lq + rh*8;
                float mu = s_mu[row], rs = s_rs[row];
                float dt = 0.f;
#pragma unroll
                for (int np=0;np<4;np++)
#pragma unroll
                    for (int h=0;h<2;h++){
                        int cb_ = wn*64 + np*16 + h*8 + l4*2;
#pragma unroll
                        for (int e=0;e<2;e++){
                            float y = (fmaxf(acc[mt][np][h][rh*2+e]+p_bias[cb_+e],0.f)-mu)*rs*p_g[cb_+e] + p_b2[cb_+e];
                            dt += y * p_lw[cb_+e];
                        }
                    }
                dt += __shfl_xor_sync(0xffffffffu, dt, 1);
                dt += __shfl_xor_sync(0xffffffffu, dt, 2);
                if (l4 == 0) redS[row*4 + wn] = dt;
            }
        __syncthreads();
        if (tid < 64){
            float d = redS[tid*4]+redS[tid*4+1]+redS[tid*4+2]+redS[tid*4+3];
            out_logdur[(size_t)b*S + s0 + tid] = d + lbb[0];
        }
    }
}

// ---------------- scan: per-row cumsum, dur-as-float, mel_len ----------------
__global__ void scan_kernel(const int* __restrict__ dur,
                            const int* __restrict__ maxlen_p,
                            float* __restrict__ out_dur,
                            float* __restrict__ out_mel)
{
    __shared__ int sa[S];
    const int b = blockIdx.x, tid = threadIdx.x;   // 1024 threads
    int v = dur[b*S + tid];
    out_dur[b*S + tid] = (float)v;
    sa[tid] = v;
    __syncthreads();
    for (int off = 1; off < S; off <<= 1) {
        int t = sa[tid];
        int u = (tid >= off) ? sa[tid - off] : 0;
        __syncthreads();
        sa[tid] = t + u;
        __syncthreads();
    }
    g_cum[b*S + tid] = sa[tid];
    if (tid == S - 1) out_mel[b] = (float)min(sa[tid], maxlen_p[0]);
}

// ---------------- length regulator gather ----------------
__global__ void __launch_bounds__(256)
gather_kernel(const float* __restrict__ x,
              const int* __restrict__ maxlen_p,
              float* __restrict__ out)
{
    __shared__ int cum[S];
    __shared__ int srcs[TT];
    const int b  = blockIdx.x / (T / TT);
    const int t0 = (blockIdx.x % (T / TT)) * TT;
    const int tid = threadIdx.x;
    for (int i = tid; i < S; i += 256) cum[i] = g_cum[b*S + i];
    __syncthreads();
    const int mel = min(cum[S-1], maxlen_p[0]);
    if (tid < TT) {
        int t = t0 + tid;
        int lo = 0, hi = S;
        while (lo < hi) {
            int mid = (lo + hi) >> 1;
            if (cum[mid] <= t) lo = mid + 1; else hi = mid;
        }
        srcs[tid] = min(lo, S - 1);
    }
    __syncthreads();
    const int wi = tid >> 5, lane = tid & 31;
    const float4* __restrict__ x4 = (const float4*)x;
    float4* __restrict__ o4 = (float4*)out;
    for (int r = wi; r < TT; r += 8) {
        int t = t0 + r;
        float4* dst = o4 + ((size_t)b*T + t) * (D/4);
        if (t < mel) {
            const float4* src = x4 + ((size_t)b*S + srcs[r]) * (D/4);
            dst[lane]      = src[lane];
            dst[lane + 32] = src[lane + 32];
        } else {
            float4 z = make_float4(0.f,0.f,0.f,0.f);
            dst[lane]      = z;
            dst[lane + 32] = z;
        }
    }
}

extern "C" void kernel_launch(void* const* d_in, const int* in_sizes, int n_in,
                              void* d_out, int out_size)
{
    const float* x        = (const float*)d_in[0];
    const int*   duration = (const int*)d_in[2];
    const int*   maxlen   = (const int*)d_in[3];
    const float* w1  = (const float*)d_in[4];
    const float* b1  = (const float*)d_in[5];
    const float* g1  = (const float*)d_in[6];
    const float* be1 = (const float*)d_in[7];
    const float* w2  = (const float*)d_in[8];
    const float* b2  = (const float*)d_in[9];
    const float* g2  = (const float*)d_in[10];
    const float* be2 = (const float*)d_in[11];
    const float* lw  = (const float*)d_in[12];
    const float* lbb = (const float*)d_in[13];

    float* out        = (float*)d_out;
    float* out_logdur = out + (size_t)B*T*D;
    float* out_dur    = out_logdur + (size_t)B*S;
    float* out_mel    = out_dur + (size_t)B*S;

    static int s_init = 0;
    static cudaStream_t s_hi1 = nullptr, s_hi2 = nullptr, s_lo = nullptr;
    static cudaEvent_t evF=nullptr, evW=nullptr, evX1=nullptr, ev01=nullptr,
                       evS=nullptr, evS2=nullptr, evM=nullptr;
    if (!s_init) {
        cudaFuncSetAttribute(conv_mma_kernel<0>, cudaFuncAttributeMaxDynamicSharedMemorySize, SMEM_TOTAL);
        cudaFuncSetAttribute(conv_mma_kernel<1>, cudaFuncAttributeMaxDynamicSharedMemorySize, SMEM_TOTAL);
        int prLo = 0, prHi = 0;
        cudaDeviceGetStreamPriorityRange(&prLo, &prHi);   // prHi = highest priority (smallest)
        bool ok = cudaStreamCreateWithPriority(&s_hi1, cudaStreamNonBlocking, prHi) == cudaSuccess &&
                  cudaStreamCreateWithPriority(&s_hi2, cudaStreamNonBlocking, prHi) == cudaSuccess &&
                  cudaStreamCreateWithPriority(&s_lo,  cudaStreamNonBlocking, prLo) == cudaSuccess &&
                  cudaEventCreateWithFlags(&evF,  cudaEventDisableTiming) == cudaSuccess &&
                  cudaEventCreateWithFlags(&evW,  cudaEventDisableTiming) == cudaSuccess &&
                  cudaEventCreateWithFlags(&evX1, cudaEventDisableTiming) == cudaSuccess &&
                  cudaEventCreateWithFlags(&ev01, cudaEventDisableTiming) == cudaSuccess &&
                  cudaEventCreateWithFlags(&evS,  cudaEventDisableTiming) == cudaSuccess &&
                  cudaEventCreateWithFlags(&evS2, cudaEventDisableTiming) == cudaSuccess &&
                  cudaEventCreateWithFlags(&evM,  cudaEventDisableTiming) == cudaSuccess;
        if (!ok) { s_hi1 = nullptr; }
        s_init = 1;
    }

    if (s_hi1) {
        // Fork all three streams from the capture-origin stream.
        // Capture rule: every cudaStreamWaitEvent must follow (host order) the
        // cudaEventRecord of that event.
        cudaEventRecord(evF, 0);
        cudaStreamWaitEvent(s_hi1, evF, 0);
        cudaStreamWaitEvent(s_hi2, evF, 0);
        cudaStreamWaitEvent(s_lo,  evF, 0);

        // Low stream: weight prep, second prep_x half, scan.
        prep_w<<<1536, 256, 0, s_lo>>>(w1, w2);
        cudaEventRecord(evW, s_lo);
        prep_x<<<4096, 256, 0, s_lo>>>(x, 4096);     // batches 16-31
        cudaEventRecord(evX1, s_lo);
        scan_kernel<<<B, 1024, 0, s_lo>>>(duration, maxlen, out_dur, out_mel);

        // High stream 1: first prep_x half, conv0 first half.
        prep_x<<<4096, 256, 0, s_hi1>>>(x, 0);       // batches 0-15
        cudaStreamWaitEvent(s_hi1, evW, 0);
        conv_mma_kernel<0><<<256, 256, SMEM_TOTAL, s_hi1>>>(b1, g1, be1, nullptr, nullptr, nullptr, 0);
        cudaEventRecord(ev01, s_hi1);

        // High stream 2: conv1 first half (needs conv0 first half).
        cudaStreamWaitEvent(s_hi2, ev01, 0);
        conv_mma_kernel<1><<<256, 256, SMEM_TOTAL, s_hi2>>>(b2, g2, be2, lw, lbb, out_logdur, 0);
        cudaEventRecord(evS2, s_hi2);

        // Low stream: gather starts only after conv0h0 is done — convs are
        // resident and get slots; gather backfills idle slots/tails.
        cudaStreamWaitEvent(s_lo, ev01, 0);
        gather_kernel<<<B*(T/TT), 256, 0, s_lo>>>(x, maxlen, out);
        cudaEventRecord(evS, s_lo);

        // High stream 1: conv0 second half (needs prep_x half 2), conv1 second half.
        cudaStreamWaitEvent(s_hi1, evX1, 0);
        conv_mma_kernel<0><<<256, 256, SMEM_TOTAL, s_hi1>>>(b1, g1, be1, nullptr, nullptr, nullptr, 16);
        conv_mma_kernel<1><<<256, 256, SMEM_TOTAL, s_hi1>>>(b2, g2, be2, lw, lbb, out_logdur, 16);
        cudaEventRecord(evM, s_hi1);

        cudaStreamWaitEvent(0, evS,  0);
        cudaStreamWaitEvent(0, evS2, 0);
        cudaStreamWaitEvent(0, evM,  0);
    } else {
        prep_x<<<4096, 256>>>(x, 0);
        prep_x<<<4096, 256>>>(x, 4096);
        prep_w<<<1536, 256>>>(w1, w2);
        conv_mma_kernel<0><<<256, 256, SMEM_TOTAL>>>(b1, g1, be1, nullptr, nullptr, nullptr, 0);
        conv_mma_kernel<0><<<256, 256, SMEM_TOTAL>>>(b1, g1, be1, nullptr, nullptr, nullptr, 16);
        conv_mma_kernel<1><<<256, 256, SMEM_TOTAL>>>(b2, g2, be2, lw, lbb, out_logdur, 0);
        conv_mma_kernel<1><<<256, 256, SMEM_TOTAL>>>(b2, g2, be2, lw, lbb, out_logdur, 16);
        scan_kernel<<<B, 1024>>>(duration, maxlen, out_dur, out_mel);
        gather_kernel<<<B*(T/TT), 256>>>(x, maxlen, out);
    }
}